// round 7
// baseline (speedup 1.0000x reference)
#include <cuda_runtime.h>
#include <cuda_bf16.h>
#include <cstdint>

#define HD   128
#define RR   8
#define NMAX 50000
#define EMAX 500000
#define NK   (NMAX * RR)        // 400000 bins
#define KTOT (HD + RR * HD)     // 1152
#define NCHUNK 36               // 1152 / 32
#define AST  40                 // smem row stride (bf16 elems): 32 + 8 pad
#define BM   64                 // M tile

// ---------------- scratch (static device globals; no allocation) ----------------
__device__ float g_agg[(size_t)NMAX * RR * HD];     // [N, 8, 128]
__device__ int   g_cnt[NK];
__device__ int   g_off[NK];
__device__ int   g_cur[NK];
__device__ int   g_bsum[512];
__device__ int   g_esrc[EMAX];
__device__ float g_h1[(size_t)NMAX * HD];
__device__ float g_h2[(size_t)NMAX * HD];
__device__ __nv_bfloat16 g_Bh1[128 * KTOT];         // B^T hi/lo: [n][k]
__device__ __nv_bfloat16 g_Bl1[128 * KTOT];
__device__ __nv_bfloat16 g_Bh2[128 * KTOT];
__device__ __nv_bfloat16 g_Bl2[128 * KTOT];

// ---------------- mma.sync / ldmatrix / cp.async helpers (base PTX, sm_80+) -----
__device__ __forceinline__ uint32_t smem_u32(const void* p) {
    return (uint32_t)__cvta_generic_to_shared(p);
}
__device__ __forceinline__ void ldsm_x4(uint32_t* r, uint32_t addr) {
    asm volatile("ldmatrix.sync.aligned.m8n8.x4.shared.b16 {%0,%1,%2,%3}, [%4];"
                 : "=r"(r[0]), "=r"(r[1]), "=r"(r[2]), "=r"(r[3]) : "r"(addr));
}
__device__ __forceinline__ void mma16816(float* d, const uint32_t* a, const uint32_t* b) {
    asm volatile(
        "mma.sync.aligned.m16n8k16.row.col.f32.bf16.bf16.f32 "
        "{%0,%1,%2,%3}, {%4,%5,%6,%7}, {%8,%9}, {%0,%1,%2,%3};"
        : "+f"(d[0]), "+f"(d[1]), "+f"(d[2]), "+f"(d[3])
        : "r"(a[0]), "r"(a[1]), "r"(a[2]), "r"(a[3]), "r"(b[0]), "r"(b[1]));
}
__device__ __forceinline__ void cp_async16(uint32_t smem_dst, const void* gptr) {
    asm volatile("cp.async.cg.shared.global [%0], [%1], 16;"
                 :: "r"(smem_dst), "l"(gptr));
}
__device__ __forceinline__ void cp_commit() {
    asm volatile("cp.async.commit_group;");
}
__device__ __forceinline__ void cp_wait0() {
    asm volatile("cp.async.wait_group 0;");
}

// ---------------- CSR build: count -> scan -> place ----------------
__global__ void count_kernel(const int* __restrict__ dst, const int* __restrict__ et,
                             int* cnt, int E) {
    int e = blockIdx.x * blockDim.x + threadIdx.x;
    if (e < E) atomicAdd(&cnt[dst[e] * RR + et[e]], 1);
}

__global__ void scan1_kernel(const int* __restrict__ cnt, int* bsum, int nk) {
    __shared__ int sh[256];
    int b = blockIdx.x, t = threadIdx.x;
    int base = b * 1024 + t * 4;
    int s = 0;
    if (base + 3 < nk) {
        int4 v = *(const int4*)(cnt + base);
        s = v.x + v.y + v.z + v.w;
    } else {
        for (int j = 0; j < 4; j++) if (base + j < nk) s += cnt[base + j];
    }
    sh[t] = s; __syncthreads();
    for (int o = 128; o; o >>= 1) { if (t < o) sh[t] += sh[t + o]; __syncthreads(); }
    if (t == 0) bsum[b] = sh[0];
}

__global__ void scan2_kernel(int* bsum, int nb) {
    __shared__ int sh[512];
    int t = threadIdx.x;
    int v = (t < nb) ? bsum[t] : 0;
    sh[t] = v; __syncthreads();
    for (int o = 1; o < 512; o <<= 1) {
        int add = (t >= o) ? sh[t - o] : 0;
        __syncthreads();
        sh[t] += add;
        __syncthreads();
    }
    if (t < nb) bsum[t] = sh[t] - v;   // exclusive
}

__global__ void scan3_kernel(const int* __restrict__ cnt, const int* __restrict__ bsum,
                             int* off, int* cur, int nk) {
    __shared__ int sh[256];
    int b = blockIdx.x, t = threadIdx.x;
    int base = b * 1024 + t * 4;
    int v[4] = {0, 0, 0, 0};
    if (base + 3 < nk) {
        int4 q = *(const int4*)(cnt + base);
        v[0] = q.x; v[1] = q.y; v[2] = q.z; v[3] = q.w;
    } else {
        for (int j = 0; j < 4; j++) if (base + j < nk) v[j] = cnt[base + j];
    }
    int ts = v[0] + v[1] + v[2] + v[3];
    sh[t] = ts; __syncthreads();
    for (int o = 1; o < 256; o <<= 1) {
        int add = (t >= o) ? sh[t - o] : 0;
        __syncthreads();
        sh[t] += add;
        __syncthreads();
    }
    int excl = sh[t] - ts + bsum[b];
    int o0 = excl, o1 = o0 + v[0], o2 = o1 + v[1], o3 = o2 + v[2];
    if (base + 3 < nk) {
        *(int4*)(off + base) = make_int4(o0, o1, o2, o3);
        *(int4*)(cur + base) = make_int4(o0, o1, o2, o3);
    } else {
        int oo[4] = {o0, o1, o2, o3};
        for (int j = 0; j < 4; j++)
            if (base + j < nk) { off[base + j] = oo[j]; cur[base + j] = oo[j]; }
    }
}

__global__ void place_kernel(const int* __restrict__ src, const int* __restrict__ dst,
                             const int* __restrict__ et, int* cur, int* esrc, int E) {
    int e = blockIdx.x * blockDim.x + threadIdx.x;
    if (e >= E) return;
    int key = dst[e] * RR + et[e];
    int pos = atomicAdd(&cur[key], 1);
    esrc[pos] = src[e];
}

// ---------------- atomic-free aggregation: warp per dst node ----------------
__global__ void agg_kernel(const float* __restrict__ feat, const int* __restrict__ esrc,
                           const int* __restrict__ off, const int* __restrict__ cur,
                           float* __restrict__ agg, int M) {
    int w = (blockIdx.x * blockDim.x + threadIdx.x) >> 5;
    int lane = threadIdx.x & 31;
    if (w >= M) return;
#pragma unroll
    for (int rel = 0; rel < RR; rel++) {
        int key = w * RR + rel;
        int s0 = off[key], s1 = cur[key];
        if (s0 >= s1) continue;
        float4 acc = make_float4(0.f, 0.f, 0.f, 0.f);
        int snext = esrc[s0];
        for (int e = s0; e < s1; e++) {
            int sc = snext;
            if (e + 1 < s1) snext = esrc[e + 1];
            float4 v = *(const float4*)(feat + (size_t)sc * HD + lane * 4);
            acc.x += v.x; acc.y += v.y; acc.z += v.z; acc.w += v.w;
        }
        *(float4*)(agg + (size_t)w * (RR * HD) + rel * HD + lane * 4) = acc;
    }
}

// weight prep: B^T[n][k] split to bf16 hi/lo.  k<128 -> root[k][n], else W[(k-128)][n]
__global__ void prep_kernel(const float* __restrict__ root, const float* __restrict__ W,
                            __nv_bfloat16* Bh, __nv_bfloat16* Bl) {
    int t = blockIdx.x * blockDim.x + threadIdx.x;
    if (t >= 128 * KTOT) return;
    int n = t / KTOT, k = t % KTOT;
    float v = (k < HD) ? root[k * HD + n] : W[(size_t)(k - HD) * HD + n];
    __nv_bfloat16 h = __float2bfloat16(v);
    float lo = v - __bfloat162float(h);
    Bh[t] = h;
    Bl[t] = __float2bfloat16(lo);
}

// ---------------- split-bf16 mma.sync GEMM, 64x128 tile, double-buffered ----------------
// out[64 x 128] = relu( [X | invcnt*agg] @ [root;W] + bias )
// InvS==0 masks empty (row,rel) slots.
__global__ __launch_bounds__(256, 3) void rgcn_mma(
    const float* __restrict__ X, const float* __restrict__ agg,
    const int* __restrict__ cnt,
    const __nv_bfloat16* __restrict__ Bh, const __nv_bfloat16* __restrict__ Bl,
    const float* __restrict__ bias, float* __restrict__ out, int M) {

    __shared__ __nv_bfloat16 Ah_s[2][BM][AST], Al_s[2][BM][AST];
    __shared__ __nv_bfloat16 Bh_s[2][128][AST], Bl_s[2][128][AST];
    __shared__ float InvS[BM * RR];

    const int tid = threadIdx.x;
    const int wid = tid >> 5;
    const int lane = tid & 31;
    const int brow = blockIdx.x * BM;

    for (int i = tid; i < BM * RR; i += 256) {
        int r = i >> 3, rel = i & 7;
        int gg = brow + r;
        int c = (gg < M) ? cnt[gg * RR + rel] : 0;
        InvS[r * RR + rel] = (c > 0) ? 1.0f / (float)c : 0.0f;
    }

    // warp tile: 2 (m) x 4 (n) warps; each warp 32 rows x 32 cols
    const int warp_m = wid & 1, warp_n = wid >> 1;
    const int mr0 = warp_m * 32, nc0 = warp_n * 32;

    const int alr = lane & 15, alc = (lane >> 4) << 3;
    const uint32_t aA0h = smem_u32(&Ah_s[0][mr0 + alr][alc]);
    const uint32_t aA1h = smem_u32(&Ah_s[0][mr0 + 16 + alr][alc]);
    const uint32_t aA0l = smem_u32(&Al_s[0][mr0 + alr][alc]);
    const uint32_t aA1l = smem_u32(&Al_s[0][mr0 + 16 + alr][alc]);
    const int blr = (lane & 7) + ((lane >> 4) << 3);
    const int blc = ((lane >> 3) & 1) << 3;
    uint32_t aBhx[2], aBlx[2];
#pragma unroll
    for (int j = 0; j < 2; j++) {
        aBhx[j] = smem_u32(&Bh_s[0][nc0 + blr + j * 16][blc]);
        aBlx[j] = smem_u32(&Bl_s[0][nc0 + blr + j * 16][blc]);
    }
    const uint32_t ABUFO = BM * AST * 2;      // bytes per A stage
    const uint32_t BBUFO = 128 * AST * 2;     // bytes per B stage

    float acc[2][4][4];
#pragma unroll
    for (int i = 0; i < 2; i++)
#pragma unroll
        for (int j = 0; j < 4; j++)
#pragma unroll
            for (int q = 0; q < 4; q++) acc[i][j][q] = 0.f;

    // A staging: thread -> (row 0..63, k-offset 0/8/16/24), 8 floats each
    const int arow = tid >> 2;
    const int aks  = (tid & 3) << 3;
    const int g    = brow + arow;
    // B staging: thread -> (n-row 0..127, k-offset 0/16)
    const int brow_t = tid >> 1;
    const int bks    = (tid & 1) << 4;

    auto loadA = [&](int c, float4* v, float& s) {
        const float* ap;
        if (c < 4) { ap = X + (size_t)g * HD + c * 32 + aks; s = 1.0f; }
        else {
            ap = agg + (size_t)g * (RR * HD) + (c - 4) * 32 + aks;
            s = InvS[arow * RR + ((c - 4) >> 2)];
        }
#pragma unroll
        for (int i = 0; i < 2; i++)
            v[i] = (g < M) ? *(const float4*)(ap + i * 4) : make_float4(0.f, 0.f, 0.f, 0.f);
    };
    auto cpB = [&](int c, int buf) {
        const char* bh = (const char*)(Bh + (size_t)brow_t * KTOT + c * 32 + bks);
        const char* bl = (const char*)(Bl + (size_t)brow_t * KTOT + c * 32 + bks);
        uint32_t dh = smem_u32(&Bh_s[buf][brow_t][bks]);
        uint32_t dl = smem_u32(&Bl_s[buf][brow_t][bks]);
        cp_async16(dh, bh);
        cp_async16(dh + 16, bh + 16);
        cp_async16(dl, bl);
        cp_async16(dl + 16, bl + 16);
    };
    auto storeA = [&](const float4* v, float s, int buf) {
        __nv_bfloat162* ah2 = (__nv_bfloat162*)&Ah_s[buf][arow][aks];
        __nv_bfloat162* al2 = (__nv_bfloat162*)&Al_s[buf][arow][aks];
#pragma unroll
        for (int i = 0; i < 2; i++) {
            float f0 = v[i].x * s, f1 = v[i].y * s, f2 = v[i].z * s, f3 = v[i].w * s;
            __nv_bfloat16 h0 = __float2bfloat16(f0), h1 = __float2bfloat16(f1);
            __nv_bfloat16 h2 = __float2bfloat16(f2), h3 = __float2bfloat16(f3);
            ah2[i * 2]     = __halves2bfloat162(h0, h1);
            ah2[i * 2 + 1] = __halves2bfloat162(h2, h3);
            al2[i * 2]     = __halves2bfloat162(
                __float2bfloat16(f0 - __bfloat162float(h0)),
                __float2bfloat16(f1 - __bfloat162float(h1)));
            al2[i * 2 + 1] = __halves2bfloat162(
                __float2bfloat16(f2 - __bfloat162float(h2)),
                __float2bfloat16(f3 - __bfloat162float(h3)));
        }
    };

    // ---- prologue ----
    {
        float4 pv[2]; float ps;
        loadA(0, pv, ps);
        cpB(0, 0);
        cp_commit();
        storeA(pv, ps, 0);
        cp_wait0();
    }
    __syncthreads();

    // ---- mainloop ----
    for (int c = 0; c < NCHUNK; c++) {
        const int buf = c & 1;
        const uint32_t ao = buf ? ABUFO : 0;
        const uint32_t bo = buf ? BBUFO : 0;

        float4 pv[2]; float ps;
        if (c + 1 < NCHUNK) {
            loadA(c + 1, pv, ps);
            cpB(c + 1, buf ^ 1);
            cp_commit();
        }

#pragma unroll
        for (int k16 = 0; k16 < 2; k16++) {
            const uint32_t akb = ao + k16 * 32;
            const uint32_t bkb = bo + k16 * 32;
            uint32_t Afh[2][4], Afl[2][4];
            ldsm_x4(Afh[0], aA0h + akb);
            ldsm_x4(Afh[1], aA1h + akb);
            ldsm_x4(Afl[0], aA0l + akb);
            ldsm_x4(Afl[1], aA1l + akb);
            uint32_t Bf[4][2];
#pragma unroll
            for (int j = 0; j < 2; j++) {
                uint32_t t[4];
                ldsm_x4(t, aBhx[j] + bkb);
                Bf[2 * j][0] = t[0]; Bf[2 * j][1] = t[1];
                Bf[2 * j + 1][0] = t[2]; Bf[2 * j + 1][1] = t[3];
            }
#pragma unroll
            for (int mf = 0; mf < 2; mf++)
#pragma unroll
                for (int nf = 0; nf < 4; nf++) mma16816(acc[mf][nf], Afh[mf], Bf[nf]);
#pragma unroll
            for (int mf = 0; mf < 2; mf++)
#pragma unroll
                for (int nf = 0; nf < 4; nf++) mma16816(acc[mf][nf], Afl[mf], Bf[nf]);
#pragma unroll
            for (int j = 0; j < 2; j++) {
                uint32_t t[4];
                ldsm_x4(t, aBlx[j] + bkb);
                Bf[2 * j][0] = t[0]; Bf[2 * j][1] = t[1];
                Bf[2 * j + 1][0] = t[2]; Bf[2 * j + 1][1] = t[3];
            }
#pragma unroll
            for (int mf = 0; mf < 2; mf++)
#pragma unroll
                for (int nf = 0; nf < 4; nf++) mma16816(acc[mf][nf], Afh[mf], Bf[nf]);
        }

        if (c + 1 < NCHUNK) {
            storeA(pv, ps, buf ^ 1);
            cp_wait0();
        }
        __syncthreads();
    }

    // ---- epilogue: bias + relu + store ----
    const int er = lane >> 2, ec = (lane & 3) * 2;
    float2 bv[4];
#pragma unroll
    for (int nf = 0; nf < 4; nf++)
        bv[nf] = *(const float2*)(bias + nc0 + nf * 8 + ec);

#pragma unroll
    for (int mf = 0; mf < 2; mf++) {
#pragma unroll
        for (int half = 0; half < 2; half++) {
            int gr = brow + mr0 + mf * 16 + half * 8 + er;
            if (gr < M) {
                float* op = out + (size_t)gr * HD + nc0 + ec;
#pragma unroll
                for (int nf = 0; nf < 4; nf++) {
                    float2 o;
                    o.x = fmaxf(acc[mf][nf][half * 2]     + bv[nf].x, 0.f);
                    o.y = fmaxf(acc[mf][nf][half * 2 + 1] + bv[nf].y, 0.f);
                    *(float2*)(op + nf * 8) = o;
                }
            }
        }
    }
}

// out[n] = dot(h2[n,:], Wc) + bc; one warp per node
__global__ void classify_kernel(const float* __restrict__ h, const float* __restrict__ Wc,
                                const float* __restrict__ bc, float* __restrict__ out, int M) {
    int t = blockIdx.x * blockDim.x + threadIdx.x;
    int n = t >> 5, lane = t & 31;
    if (n >= M) return;
    float4 v = *(const float4*)(h + (size_t)n * HD + lane * 4);
    float4 w = *(const float4*)(Wc + lane * 4);
    float s = v.x * w.x + v.y * w.y + v.z * w.z + v.w * w.w;
#pragma unroll
    for (int o = 16; o; o >>= 1) s += __shfl_xor_sync(0xffffffffu, s, o);
    if (lane == 0) out[n] = s + bc[0];
}

// ---------------- launch ----------------
extern "C" void kernel_launch(void* const* d_in, const int* in_sizes, int n_in,
                              void* d_out, int out_size) {
    const float* x  = (const float*)d_in[0];
    const int*   ei = (const int*)d_in[1];
    const int*   et = (const int*)d_in[2];
    const float* W1 = (const float*)d_in[3];
    const float* r1 = (const float*)d_in[4];
    const float* b1 = (const float*)d_in[5];
    const float* W2 = (const float*)d_in[6];
    const float* r2 = (const float*)d_in[7];
    const float* b2 = (const float*)d_in[8];
    const float* Wc = (const float*)d_in[9];
    const float* bc = (const float*)d_in[10];

    int M = in_sizes[0] / HD;    // 50000
    int E = in_sizes[1] / 2;     // 500000
    const int* src = ei;
    const int* dst = ei + E;

    float *agg, *h1, *h2;
    int *cnt, *off, *cur, *bsum, *esrc;
    __nv_bfloat16 *Bh1, *Bl1, *Bh2, *Bl2;
    cudaGetSymbolAddress((void**)&agg, g_agg);
    cudaGetSymbolAddress((void**)&cnt, g_cnt);
    cudaGetSymbolAddress((void**)&off, g_off);
    cudaGetSymbolAddress((void**)&cur, g_cur);
    cudaGetSymbolAddress((void**)&bsum, g_bsum);
    cudaGetSymbolAddress((void**)&esrc, g_esrc);
    cudaGetSymbolAddress((void**)&h1, g_h1);
    cudaGetSymbolAddress((void**)&h2, g_h2);
    cudaGetSymbolAddress((void**)&Bh1, g_Bh1);
    cudaGetSymbolAddress((void**)&Bl1, g_Bl1);
    cudaGetSymbolAddress((void**)&Bh2, g_Bh2);
    cudaGetSymbolAddress((void**)&Bl2, g_Bl2);

    int nk = M * RR;
    int nb = (nk + 1023) / 1024;
    int mblocks = (M + BM - 1) / BM;              // 782
    int eblocks = (E + 255) / 256;
    int pblocks = (128 * KTOT + 255) / 256;
    int ablocks = (M * 32 + 255) / 256;

    // weight prep (static per call)
    prep_kernel<<<pblocks, 256>>>(r1, W1, Bh1, Bl1);
    prep_kernel<<<pblocks, 256>>>(r2, W2, Bh2, Bl2);

    // ---- CSR build (shared by both layers) ----
    cudaMemsetAsync(cnt, 0, nk * sizeof(int));
    count_kernel<<<eblocks, 256>>>(dst, et, cnt, E);
    scan1_kernel<<<nb, 256>>>(cnt, bsum, nk);
    scan2_kernel<<<1, 512>>>(bsum, nb);
    scan3_kernel<<<nb, 256>>>(cnt, bsum, off, cur, nk);
    place_kernel<<<eblocks, 256>>>(src, dst, et, cur, esrc, E);

    // ---- layer 1 ----
    agg_kernel<<<ablocks, 256>>>(x, esrc, off, cur, agg, M);
    rgcn_mma<<<mblocks, 256>>>(x, agg, cnt, Bh1, Bl1, b1, h1, M);

    // ---- layer 2 ----
    agg_kernel<<<ablocks, 256>>>(h1, esrc, off, cur, agg, M);
    rgcn_mma<<<mblocks, 256>>>(h1, agg, cnt, Bh2, Bl2, b2, h2, M);

    // ---- classifier ----
    classify_kernel<<<((M * 32) + 255) / 256, 256>>>(h2, Wc, bc, (float*)d_out, M);
}